// round 4
// baseline (speedup 1.0000x reference)
#include <cuda_runtime.h>
#include <math.h>

#define Xn 262144
#define Bn 64
#define Hn 256
#define THRF 1e-6f
#define NT 512            // threads per block
#define TILE_FLOATS 16384 // 64KB weight tile
#define NCNT 20           // count blocks (grid = 128 + 20 = 148, single wave)

__device__ __forceinline__ float gelu_f(float v) {
    return 0.5f * v * (1.0f + erff(v * 0.70710678118654752f));
}

__device__ __forceinline__ void cpa16(float* dst, const float* src) {
    unsigned d = (unsigned)__cvta_generic_to_shared(dst);
    asm volatile("cp.async.cg.shared.global [%0], [%1], 16;\n" :: "r"(d), "l"(src));
}
#define CPA_COMMIT() asm volatile("cp.async.commit_group;\n" ::)
#define CPA_WAIT(n)  asm volatile("cp.async.wait_group %0;\n" :: "n"(n))

// copy one 16384-float tile: 8 float4 per thread, coalesced; commits a group
__device__ __forceinline__ void copy_tile(float* dst, const float* src, int tid) {
    #pragma unroll
    for (int j = 0; j < 8; j++)
        cpa16(dst + (tid + j * NT) * 4, src + (tid + j * NT) * 4);
    CPA_COMMIT();
}

// LN stats over 4 tokens x 256; warp t (t<4) reduces token t
__device__ __forceinline__ void ln_stats(const float* buf, float* s_mu, float* s_rs, int tid) {
    int w = tid >> 5, lane = tid & 31;
    if (w < 4) {
        float s1 = 0.f, s2 = 0.f;
        #pragma unroll
        for (int j = 0; j < 8; j++) {
            float v = buf[w * Hn + lane + 32 * j];
            s1 += v;
            s2 = fmaf(v, v, s2);
        }
        #pragma unroll
        for (int o = 16; o; o >>= 1) {
            s1 += __shfl_xor_sync(0xffffffffu, s1, o);
            s2 += __shfl_xor_sync(0xffffffffu, s2, o);
        }
        if (lane == 0) {
            float mu = s1 * (1.f / 256.f);
            float var = fmaxf(s2 * (1.f / 256.f) - mu * mu, 0.f);
            s_mu[w] = mu;
            s_rs[w] = rsqrtf(var + 1e-5f);
        }
    }
    __syncthreads();
}

__global__ void __launch_bounds__(NT, 1) fused_all(
    const float* __restrict__ x,
    const float* __restrict__ w_in,  const float* __restrict__ b_in,
    const float* __restrict__ ln_in_g, const float* __restrict__ ln_in_b,
    const float* __restrict__ rb_ln_g, const float* __restrict__ rb_ln_b,
    const float* __restrict__ rb_w1,  const float* __restrict__ rb_b1,
    const float* __restrict__ rb_w2,  const float* __restrict__ rb_b2,
    const float* __restrict__ out_ln_g, const float* __restrict__ out_ln_b,
    const float* __restrict__ out_w1, const float* __restrict__ out_b1,
    const float* __restrict__ out_w2, const float* __restrict__ out_b2,
    float* __restrict__ out)
{
    const int tid = threadIdx.x;

    // ============ COUNT BLOCKS (128..147): 3-4 batch rows each ============
    if (blockIdx.x >= 128) {
        int blk = blockIdx.x - 128;
        __shared__ int cw[16];
        for (int b = blk; b < Bn; b += NCNT) {
            const float*  d  = x + (size_t)b * 2 * Xn;
            const float4* d4 = (const float4*)d;
            int cnt = 0;
            #pragma unroll 4
            for (int i = tid; i < Xn / 4; i += NT) {
                float4 v = d4[i];
                float nx = 0.f;
                bool has_nx = (i < Xn / 4 - 1);
                if (has_nx) nx = d[4 * i + 4];
                cnt += (fabsf(v.x - v.y) > THRF);
                cnt += (fabsf(v.y - v.z) > THRF);
                cnt += (fabsf(v.z - v.w) > THRF);
                if (has_nx) cnt += (fabsf(v.w - nx) > THRF);
            }
            #pragma unroll
            for (int o = 16; o; o >>= 1) cnt += __shfl_xor_sync(0xffffffffu, cnt, o);
            if ((tid & 31) == 0) cw[tid >> 5] = cnt;
            __syncthreads();
            if (tid == 0) {
                int s = 0;
                #pragma unroll
                for (int w = 0; w < 16; w++) s += cw[w];
                out[Bn * 48 + b] = (float)s;
            }
            __syncthreads();
        }
        return;
    }

    // ============ MLP BLOCKS (0..127): batch b, 4 tokens ============
    const int b     = blockIdx.x >> 1;
    const int kbase = (blockIdx.x & 1) * 4;
    const float* d  = x + (size_t)b * 2 * Xn;
    const float* cr = d + Xn;

    extern __shared__ float smem[];
    float* wb0  = smem;                 // 16384 floats
    float* wb1  = smem + TILE_FLOATS;   // 16384 floats
    float* s_h  = smem + 2 * TILE_FLOATS;          // 4*256
    float* s_zv = s_h + 4 * Hn;                    // 4*256
    float* s_zz = s_zv + 4 * Hn;                   // 4*512

    __shared__ float s_mu[4], s_rs[4];
    __shared__ float s_tk[2][4];
    __shared__ unsigned s_wm[16], s_vm[16];
    __shared__ int s_idx[8], s_non[8];
    __shared__ int s_nd, s_nn, s_done;

    // prefetch very first weight tile immediately (hides behind front-finding)
    copy_tile(wb0, rb_w1, tid);

    // ---- phase 0: find first 8 discontinuities (ordered) ----
    if (tid == 0) { s_nd = 0; s_nn = 0; s_done = 0; }
    __syncthreads();
    for (int base = 0; base < Xn - 1; base += NT) {
        int i = base + tid;
        bool valid = (i < Xn - 1);
        bool disc = valid && (fabsf(d[i] - d[i + 1]) > THRF);
        unsigned m  = __ballot_sync(0xffffffffu, disc);
        unsigned vm = __ballot_sync(0xffffffffu, valid);
        if ((tid & 31) == 0) { s_wm[tid >> 5] = m; s_vm[tid >> 5] = vm; }
        __syncthreads();
        if (tid == 0) {
            for (int w = 0; w < 16 && s_nd < 8; w++) {
                unsigned mm = s_wm[w], vv = s_vm[w];
                int ib = base + w * 32;
                while (vv) {
                    int lane = __ffs(vv) - 1;
                    vv &= vv - 1;
                    int idx = ib + lane;
                    if ((mm >> lane) & 1u) {
                        if (s_nd < 8) {
                            s_idx[s_nd++] = idx;
                            if (s_nd >= 8) break;
                        }
                    } else {
                        if (s_nn < 8) s_non[s_nn++] = idx;
                    }
                }
            }
            if (s_nd >= 8) s_done = 1;
        }
        __syncthreads();
        if (s_done) break;
    }
    if (tid < 4) {
        int k = kbase + tid;
        int nd = s_nd;
        int i; float vf;
        if (k < nd) { i = s_idx[k]; vf = 1.0f; }
        else        { i = s_non[k - nd]; vf = 0.0f; }
        float uL = d[i], uR = d[i + 1];
        float fc = 0.5f * (cr[i] + cr[i + 1]);
        s_tk[0][tid] = uL;
        s_tk[1][tid] = uR;
        int base = b * 48;
        out[base + 16 + k] = uL;
        out[base + 24 + k] = uR;
        out[base + 32 + k] = fc;
        out[base + 40 + k] = vf;
    }
    __syncthreads();

    // ---- input layer (threads < 256 active) ----
    if (tid < Hn) {
        int n = tid;
        float wv[6];
        #pragma unroll
        for (int f = 0; f < 6; f++) wv[f] = w_in[f * Hn + n];
        float bi = b_in[n];
        #pragma unroll
        for (int t = 0; t < 4; t++) {
            float uL = s_tk[0][t], uR = s_tk[1][t];
            float df = uL - uR;
            float sg = (df > 0.f) ? 1.f : ((df < 0.f) ? -1.f : 0.f);
            float pre = bi;
            pre = fmaf(uL, wv[0], pre);
            pre = fmaf(uR, wv[1], pre);
            pre = fmaf(df, wv[2], pre);
            pre = fmaf(fabsf(df), wv[3], pre);
            pre = fmaf(0.5f * (uL + uR), wv[4], pre);
            pre = fmaf(sg, wv[5], pre);
            s_zv[t * Hn + n] = pre;
        }
    }
    __syncthreads();
    ln_stats(s_zv, s_mu, s_rs, tid);
    if (tid < Hn) {
        float lg = ln_in_g[tid], lb = ln_in_b[tid];
        #pragma unroll
        for (int t = 0; t < 4; t++)
            s_h[t * Hn + tid] = gelu_f((s_zv[t * Hn + tid] - s_mu[t]) * s_rs[t] * lg + lb);
    }
    __syncthreads();

    // ---- 3 residual blocks; weight tiles stream through a never-drained
    //      cp.async double-buffer chain (next phase's tile0 prefetched at
    //      current phase's last tile) ----
    for (int i = 0; i < 3; i++) {
        ln_stats(s_h, s_mu, s_rs, tid);
        if (tid < Hn) {
            float g = rb_ln_g[i * Hn + tid], bb = rb_ln_b[i * Hn + tid];
            #pragma unroll
            for (int t = 0; t < 4; t++)
                s_zv[t * Hn + tid] = (s_h[t * Hn + tid] - s_mu[t]) * s_rs[t] * g + bb;
        }
        __syncthreads();

        const float* W1 = rb_w1 + (size_t)i * Hn * 2 * Hn; // [256][512]
        const float* W2 = rb_w2 + (size_t)i * 2 * Hn * Hn; // [512][256]
        const float* Wafter = (i < 2) ? (rb_w1 + (size_t)(i + 1) * Hn * 2 * Hn) : out_w1;

        // ===== GEMM1: zz[t][c] = gelu( sum_k z[t][k]*W1[k][c] + b1[c] ), c = tid
        {
            float acc0 = 0, acc1 = 0, acc2 = 0, acc3 = 0;
            #pragma unroll
            for (int t8 = 0; t8 < 8; t8++) {
                float* cur = (t8 & 1) ? wb1 : wb0;
                float* nxt = (t8 & 1) ? wb0 : wb1;
                if (t8 + 1 < 8) copy_tile(nxt, W1 + (t8 + 1) * TILE_FLOATS, tid);
                else            copy_tile(nxt, W2, tid);   // prefetch GEMM2 tile0
                CPA_WAIT(1);
                __syncthreads();
                int k0 = t8 * 32;
                #pragma unroll
                for (int kk = 0; kk < 8; kk++) {
                    float4 z0 = *(const float4*)&s_zv[0 * Hn + k0 + kk * 4];
                    float4 z1 = *(const float4*)&s_zv[1 * Hn + k0 + kk * 4];
                    float4 z2 = *(const float4*)&s_zv[2 * Hn + k0 + kk * 4];
                    float4 z3 = *(const float4*)&s_zv[3 * Hn + k0 + kk * 4];
                    float w0 = cur[(kk * 4 + 0) * 512 + tid];
                    float w1v = cur[(kk * 4 + 1) * 512 + tid];
                    float w2v = cur[(kk * 4 + 2) * 512 + tid];
                    float w3v = cur[(kk * 4 + 3) * 512 + tid];
                    acc0 = fmaf(z0.x, w0, acc0); acc0 = fmaf(z0.y, w1v, acc0);
                    acc0 = fmaf(z0.z, w2v, acc0); acc0 = fmaf(z0.w, w3v, acc0);
                    acc1 = fmaf(z1.x, w0, acc1); acc1 = fmaf(z1.y, w1v, acc1);
                    acc1 = fmaf(z1.z, w2v, acc1); acc1 = fmaf(z1.w, w3v, acc1);
                    acc2 = fmaf(z2.x, w0, acc2); acc2 = fmaf(z2.y, w1v, acc2);
                    acc2 = fmaf(z2.z, w2v, acc2); acc2 = fmaf(z2.w, w3v, acc2);
                    acc3 = fmaf(z3.x, w0, acc3); acc3 = fmaf(z3.y, w1v, acc3);
                    acc3 = fmaf(z3.z, w2v, acc3); acc3 = fmaf(z3.w, w3v, acc3);
                }
                __syncthreads();
            }
            float bb = rb_b1[i * 2 * Hn + tid];
            s_zz[0 * 512 + tid] = gelu_f(acc0 + bb);
            s_zz[1 * 512 + tid] = gelu_f(acc1 + bb);
            s_zz[2 * 512 + tid] = gelu_f(acc2 + bb);
            s_zz[3 * 512 + tid] = gelu_f(acc3 + bb);
            __syncthreads();
        }

        // ===== GEMM2: h[t][c] += sum_k zz[t][k]*W2[k][c] + b2[c]; split-K by 2
        {
            const int col = tid & 255, half = tid >> 8;
            float acc0 = 0, acc1 = 0, acc2 = 0, acc3 = 0;
            #pragma unroll
            for (int t8 = 0; t8 < 8; t8++) {
                float* cur = (t8 & 1) ? wb1 : wb0;
                float* nxt = (t8 & 1) ? wb0 : wb1;
                if (t8 + 1 < 8) copy_tile(nxt, W2 + (t8 + 1) * TILE_FLOATS, tid);
                else            copy_tile(nxt, Wafter, tid);  // next phase tile0
                CPA_WAIT(1);
                __syncthreads();
                int klocal = half * 32;
                int kglob  = t8 * 64 + klocal;
                #pragma unroll
                for (int kk = 0; kk < 8; kk++) {
                    float4 z0 = *(const float4*)&s_zz[0 * 512 + kglob + kk * 4];
                    float4 z1 = *(const float4*)&s_zz[1 * 512 + kglob + kk * 4];
                    float4 z2 = *(const float4*)&s_zz[2 * 512 + kglob + kk * 4];
                    float4 z3 = *(const float4*)&s_zz[3 * 512 + kglob + kk * 4];
                    float w0 = cur[(klocal + kk * 4 + 0) * 256 + col];
                    float w1v = cur[(klocal + kk * 4 + 1) * 256 + col];
                    float w2v = cur[(klocal + kk * 4 + 2) * 256 + col];
                    float w3v = cur[(klocal + kk * 4 + 3) * 256 + col];
                    acc0 = fmaf(z0.x, w0, acc0); acc0 = fmaf(z0.y, w1v, acc0);
                    acc0 = fmaf(z0.z, w2v, acc0); acc0 = fmaf(z0.w, w3v, acc0);
                    acc1 = fmaf(z1.x, w0, acc1); acc1 = fmaf(z1.y, w1v, acc1);
                    acc1 = fmaf(z1.z, w2v, acc1); acc1 = fmaf(z1.w, w3v, acc1);
                    acc2 = fmaf(z2.x, w0, acc2); acc2 = fmaf(z2.y, w1v, acc2);
                    acc2 = fmaf(z2.z, w2v, acc2); acc2 = fmaf(z2.w, w3v, acc2);
                    acc3 = fmaf(z3.x, w0, acc3); acc3 = fmaf(z3.y, w1v, acc3);
                    acc3 = fmaf(z3.z, w2v, acc3); acc3 = fmaf(z3.w, w3v, acc3);
                }
                __syncthreads();
            }
            if (half == 0) {
                s_zv[0 * Hn + col] = acc0;
                s_zv[1 * Hn + col] = acc1;
                s_zv[2 * Hn + col] = acc2;
                s_zv[3 * Hn + col] = acc3;
            }
            __syncthreads();
            if (half == 1) {
                float bq = rb_b2[i * Hn + col];
                s_h[0 * Hn + col] += s_zv[0 * Hn + col] + acc0 + bq;
                s_h[1 * Hn + col] += s_zv[1 * Hn + col] + acc1 + bq;
                s_h[2 * Hn + col] += s_zv[2 * Hn + col] + acc2 + bq;
                s_h[3 * Hn + col] += s_zv[3 * Hn + col] + acc3 + bq;
            }
            __syncthreads();
        }
    }

    // ---- output head ----
    ln_stats(s_h, s_mu, s_rs, tid);
    if (tid < Hn) {
        float og = out_ln_g[tid], ob = out_ln_b[tid];
        #pragma unroll
        for (int t = 0; t < 4; t++)
            s_zv[t * Hn + tid] = (s_h[t * Hn + tid] - s_mu[t]) * s_rs[t] * og + ob;
    }
    __syncthreads();

    // a1 = gelu(z @ out_w1 + b1): out_w1 [256][128], 2 tiles of 128 rows;
    // tile0 already in flight (prefetched by last GEMM2)
    {
        const int col = tid & 127, kq = tid >> 7;
        float p0 = 0, p1 = 0, p2 = 0, p3 = 0;
        #pragma unroll
        for (int t8 = 0; t8 < 2; t8++) {
            float* cur = (t8 & 1) ? wb1 : wb0;
            float* nxt = (t8 & 1) ? wb0 : wb1;
            if (t8 == 0) { copy_tile(nxt, out_w1 + TILE_FLOATS, tid); CPA_WAIT(1); }
            else         { CPA_WAIT(0); }
            __syncthreads();
            int kb = kq * 32;                 // row within tile
            int zg = t8 * 128 + kb;           // z index
            #pragma unroll
            for (int kk = 0; kk < 8; kk++) {
                float4 z0 = *(const float4*)&s_zv[0 * Hn + zg + kk * 4];
                float4 z1 = *(const float4*)&s_zv[1 * Hn + zg + kk * 4];
                float4 z2 = *(const float4*)&s_zv[2 * Hn + zg + kk * 4];
                float4 z3 = *(const float4*)&s_zv[3 * Hn + zg + kk * 4];
                float w0 = cur[(kb + kk * 4 + 0) * 128 + col];
                float w1v = cur[(kb + kk * 4 + 1) * 128 + col];
                float w2v = cur[(kb + kk * 4 + 2) * 128 + col];
                float w3v = cur[(kb + kk * 4 + 3) * 128 + col];
                p0 = fmaf(z0.x, w0, p0); p0 = fmaf(z0.y, w1v, p0);
                p0 = fmaf(z0.z, w2v, p0); p0 = fmaf(z0.w, w3v, p0);
                p1 = fmaf(z1.x, w0, p1); p1 = fmaf(z1.y, w1v, p1);
                p1 = fmaf(z1.z, w2v, p1); p1 = fmaf(z1.w, w3v, p1);
                p2 = fmaf(z2.x, w0, p2); p2 = fmaf(z2.y, w1v, p2);
                p2 = fmaf(z2.z, w2v, p2); p2 = fmaf(z2.w, w3v, p2);
                p3 = fmaf(z3.x, w0, p3); p3 = fmaf(z3.y, w1v, p3);
                p3 = fmaf(z3.z, w2v, p3); p3 = fmaf(z3.w, w3v, p3);
            }
            __syncthreads();
        }
        s_zz[0 * 512 + kq * 128 + col] = p0;
        s_zz[1 * 512 + kq * 128 + col] = p1;
        s_zz[2 * 512 + kq * 128 + col] = p2;
        s_zz[3 * 512 + kq * 128 + col] = p3;
        __syncthreads();
        if (tid < 128) {
            float bo = out_b1[tid];
            #pragma unroll
            for (int t = 0; t < 4; t++) {
                float s = s_zz[t * 512 + tid] + s_zz[t * 512 + 128 + tid]
                        + s_zz[t * 512 + 256 + tid] + s_zz[t * 512 + 384 + tid] + bo;
                s_zv[t * Hn + tid] = gelu_f(s);
            }
        }
        __syncthreads();
    }

    // speed = a1 @ out_w2 + out_b2: warps 0..7 -> (token, col)
    {
        int w = tid >> 5, lane = tid & 31;
        if (w < 8) {
            int t = w >> 1, cc = w & 1;
            float s = 0.f;
            s = fmaf(s_zv[t * Hn + lane],      out_w2[lane * 2 + cc],        s);
            s = fmaf(s_zv[t * Hn + lane + 32], out_w2[(lane + 32) * 2 + cc], s);
            s = fmaf(s_zv[t * Hn + lane + 64], out_w2[(lane + 64) * 2 + cc], s);
            s = fmaf(s_zv[t * Hn + lane + 96], out_w2[(lane + 96) * 2 + cc], s);
            #pragma unroll
            for (int o = 16; o; o >>= 1) s += __shfl_xor_sync(0xffffffffu, s, o);
            if (lane == 0)
                out[b * 48 + cc * 8 + (kbase + t)] = s + out_b2[cc];
        }
    }
}

extern "C" void kernel_launch(void* const* d_in, const int* in_sizes, int n_in,
                              void* d_out, int out_size) {
    const float* x        = (const float*)d_in[0];
    const float* w_in     = (const float*)d_in[1];
    const float* b_in     = (const float*)d_in[2];
    const float* ln_in_g  = (const float*)d_in[3];
    const float* ln_in_b  = (const float*)d_in[4];
    const float* rb_ln_g  = (const float*)d_in[5];
    const float* rb_ln_b  = (const float*)d_in[6];
    const float* rb_w1    = (const float*)d_in[7];
    const float* rb_b1    = (const float*)d_in[8];
    const float* rb_w2    = (const float*)d_in[9];
    const float* rb_b2    = (const float*)d_in[10];
    const float* out_ln_g = (const float*)d_in[11];
    const float* out_ln_b = (const float*)d_in[12];
    const float* out_w1   = (const float*)d_in[13];
    const float* out_b1   = (const float*)d_in[14];
    const float* out_w2   = (const float*)d_in[15];
    const float* out_b2   = (const float*)d_in[16];
    float* out = (float*)d_out;

    const int smem_bytes = (2 * TILE_FLOATS + 4 * Hn + 4 * Hn + 4 * 512) * sizeof(float);
    cudaFuncSetAttribute(fused_all, cudaFuncAttributeMaxDynamicSharedMemorySize, smem_bytes);

    fused_all<<<148, NT, smem_bytes>>>(x, w_in, b_in, ln_in_g, ln_in_b,
                                       rb_ln_g, rb_ln_b, rb_w1, rb_b1, rb_w2, rb_b2,
                                       out_ln_g, out_ln_b, out_w1, out_b1, out_w2, out_b2,
                                       out);
}

// round 5
// speedup vs baseline: 1.6922x; 1.6922x over previous
#include <cuda_runtime.h>
#include <math.h>

#define Xn 262144
#define Bn 64
#define Hn 256
#define THRF 1e-6f
#define NT 512            // threads per block
#define TILE_FLOATS 16384 // 64KB weight tile
#define NTILES 50         // 3 residual blocks * 16 + 2 head tiles
#define NCNT 20           // count blocks (grid = 128 + 20 = 148, single wave)

__device__ __forceinline__ float gelu_f(float v) {
    return 0.5f * v * (1.0f + erff(v * 0.70710678118654752f));
}

__device__ __forceinline__ void cpa16(float* dst, const float* src) {
    unsigned d = (unsigned)__cvta_generic_to_shared(dst);
    asm volatile("cp.async.cg.shared.global [%0], [%1], 16;\n" :: "r"(d), "l"(src));
}
#define CPA_COMMIT() asm volatile("cp.async.commit_group;\n" ::)
#define CPA_WAIT(n)  asm volatile("cp.async.wait_group %0;\n" :: "n"(n))

// copy one 16384-float tile: 8 float4 per thread, coalesced; commits a group
__device__ __forceinline__ void copy_tile(float* dst, const float* src, int tid) {
    #pragma unroll
    for (int j = 0; j < 8; j++)
        cpa16(dst + (tid + j * NT) * 4, src + (tid + j * NT) * 4);
    CPA_COMMIT();
}

// LN stats over 4 tokens x 256; warp t (t<4) reduces token t
__device__ __forceinline__ void ln_stats(const float* buf, float* s_mu, float* s_rs, int tid) {
    int w = tid >> 5, lane = tid & 31;
    if (w < 4) {
        float s1 = 0.f, s2 = 0.f;
        #pragma unroll
        for (int j = 0; j < 8; j++) {
            float v = buf[w * Hn + lane + 32 * j];
            s1 += v;
            s2 = fmaf(v, v, s2);
        }
        #pragma unroll
        for (int o = 16; o; o >>= 1) {
            s1 += __shfl_xor_sync(0xffffffffu, s1, o);
            s2 += __shfl_xor_sync(0xffffffffu, s2, o);
        }
        if (lane == 0) {
            float mu = s1 * (1.f / 256.f);
            float var = fmaxf(s2 * (1.f / 256.f) - mu * mu, 0.f);
            s_mu[w] = mu;
            s_rs[w] = rsqrtf(var + 1e-5f);
        }
    }
    __syncthreads();
}

__global__ void __launch_bounds__(NT, 1) fused_all(
    const float* __restrict__ x,
    const float* __restrict__ w_in,  const float* __restrict__ b_in,
    const float* __restrict__ ln_in_g, const float* __restrict__ ln_in_b,
    const float* __restrict__ rb_ln_g, const float* __restrict__ rb_ln_b,
    const float* __restrict__ rb_w1,  const float* __restrict__ rb_b1,
    const float* __restrict__ rb_w2,  const float* __restrict__ rb_b2,
    const float* __restrict__ out_ln_g, const float* __restrict__ out_ln_b,
    const float* __restrict__ out_w1, const float* __restrict__ out_b1,
    const float* __restrict__ out_w2, const float* __restrict__ out_b2,
    float* __restrict__ out)
{
    const int tid = threadIdx.x;

    // ============ COUNT BLOCKS (128..147): 3-4 batch rows, MLP-rich ============
    if (blockIdx.x >= 128) {
        int blk = blockIdx.x - 128;
        __shared__ int cw[16];
        for (int b = blk; b < Bn; b += NCNT) {
            const float*  d  = x + (size_t)b * 2 * Xn;
            const float4* d4 = (const float4*)d;
            int cnt = 0;
            // each thread: 16 contiguous floats + boundary scalar per iter
            #pragma unroll 2
            for (int it = 0; it < Xn / (NT * 16); it++) {
                int i4 = tid * 4 + it * NT * 4;   // float4 index
                float4 a0 = d4[i4 + 0];
                float4 a1 = d4[i4 + 1];
                float4 a2 = d4[i4 + 2];
                float4 a3 = d4[i4 + 3];
                int j0 = i4 * 4;
                bool hb = (j0 + 16) < Xn;
                float nxt = hb ? d[j0 + 16] : 0.f;
                cnt += (fabsf(a0.x - a0.y) > THRF);
                cnt += (fabsf(a0.y - a0.z) > THRF);
                cnt += (fabsf(a0.z - a0.w) > THRF);
                cnt += (fabsf(a0.w - a1.x) > THRF);
                cnt += (fabsf(a1.x - a1.y) > THRF);
                cnt += (fabsf(a1.y - a1.z) > THRF);
                cnt += (fabsf(a1.z - a1.w) > THRF);
                cnt += (fabsf(a1.w - a2.x) > THRF);
                cnt += (fabsf(a2.x - a2.y) > THRF);
                cnt += (fabsf(a2.y - a2.z) > THRF);
                cnt += (fabsf(a2.z - a2.w) > THRF);
                cnt += (fabsf(a2.w - a3.x) > THRF);
                cnt += (fabsf(a3.x - a3.y) > THRF);
                cnt += (fabsf(a3.y - a3.z) > THRF);
                cnt += (fabsf(a3.z - a3.w) > THRF);
                cnt += (hb && (fabsf(a3.w - nxt) > THRF));
            }
            #pragma unroll
            for (int o = 16; o; o >>= 1) cnt += __shfl_xor_sync(0xffffffffu, cnt, o);
            if ((tid & 31) == 0) cw[tid >> 5] = cnt;
            __syncthreads();
            if (tid == 0) {
                int s = 0;
                #pragma unroll
                for (int w = 0; w < 16; w++) s += cw[w];
                out[Bn * 48 + b] = (float)s;
            }
            __syncthreads();
        }
        return;
    }

    // ============ MLP BLOCKS (0..127): batch b, 4 tokens ============
    const int b     = blockIdx.x >> 1;
    const int kbase = (blockIdx.x & 1) * 4;
    const float* d  = x + (size_t)b * 2 * Xn;
    const float* cr = d + Xn;

    extern __shared__ float smem[];
    float* s_h  = smem + 3 * TILE_FLOATS;          // 4*256
    float* s_zv = s_h + 4 * Hn;                    // 4*256
    float* s_zz = s_zv + 4 * Hn;                   // 4*512

    __shared__ const float* s_tiles[NTILES];
    __shared__ float s_mu[4], s_rs[4];
    __shared__ float s_tk[2][4];
    __shared__ unsigned s_wm[16], s_vm[16];
    __shared__ int s_idx[8], s_non[8];
    __shared__ int s_nd, s_nn, s_done;

    // issue first two weight tiles immediately (hidden behind front-finding)
    copy_tile(smem + 0 * TILE_FLOATS, rb_w1, tid);
    copy_tile(smem + 1 * TILE_FLOATS, rb_w1 + TILE_FLOATS, tid);
    int gt = 2;  // next tile index to issue

    // build flat tile-pointer schedule
    if (tid < NTILES) {
        int j = tid;
        const float* p;
        if (j < 48) {
            int ph = j >> 4, w = j & 15;
            p = (w < 8) ? rb_w1 + (size_t)ph * 131072 + (size_t)w * TILE_FLOATS
                        : rb_w2 + (size_t)ph * 131072 + (size_t)(w - 8) * TILE_FLOATS;
        } else {
            p = out_w1 + (size_t)(j - 48) * TILE_FLOATS;
        }
        s_tiles[j] = p;
    }

    // ---- phase 0: find first 8 discontinuities (ordered) ----
    if (tid == 0) { s_nd = 0; s_nn = 0; s_done = 0; }
    __syncthreads();
    for (int base = 0; base < Xn - 1; base += NT) {
        int i = base + tid;
        bool valid = (i < Xn - 1);
        bool disc = valid && (fabsf(d[i] - d[i + 1]) > THRF);
        unsigned m  = __ballot_sync(0xffffffffu, disc);
        unsigned vm = __ballot_sync(0xffffffffu, valid);
        if ((tid & 31) == 0) { s_wm[tid >> 5] = m; s_vm[tid >> 5] = vm; }
        __syncthreads();
        if (tid == 0) {
            for (int w = 0; w < 16 && s_nd < 8; w++) {
                unsigned mm = s_wm[w], vv = s_vm[w];
                int ib = base + w * 32;
                while (vv) {
                    int lane = __ffs(vv) - 1;
                    vv &= vv - 1;
                    int idx = ib + lane;
                    if ((mm >> lane) & 1u) {
                        if (s_nd < 8) {
                            s_idx[s_nd++] = idx;
                            if (s_nd >= 8) break;
                        }
                    } else {
                        if (s_nn < 8) s_non[s_nn++] = idx;
                    }
                }
            }
            if (s_nd >= 8) s_done = 1;
        }
        __syncthreads();
        if (s_done) break;
    }
    if (tid < 4) {
        int k = kbase + tid;
        int nd = s_nd;
        int i; float vf;
        if (k < nd) { i = s_idx[k]; vf = 1.0f; }
        else        { i = s_non[k - nd]; vf = 0.0f; }
        float uL = d[i], uR = d[i + 1];
        float fc = 0.5f * (cr[i] + cr[i + 1]);
        s_tk[0][tid] = uL;
        s_tk[1][tid] = uR;
        int base = b * 48;
        out[base + 16 + k] = uL;
        out[base + 24 + k] = uR;
        out[base + 32 + k] = fc;
        out[base + 40 + k] = vf;
    }
    __syncthreads();

    // ---- input layer (threads < 256 active) ----
    if (tid < Hn) {
        int n = tid;
        float wv[6];
        #pragma unroll
        for (int f = 0; f < 6; f++) wv[f] = w_in[f * Hn + n];
        float bi = b_in[n];
        #pragma unroll
        for (int t = 0; t < 4; t++) {
            float uL = s_tk[0][t], uR = s_tk[1][t];
            float df = uL - uR;
            float sg = (df > 0.f) ? 1.f : ((df < 0.f) ? -1.f : 0.f);
            float pre = bi;
            pre = fmaf(uL, wv[0], pre);
            pre = fmaf(uR, wv[1], pre);
            pre = fmaf(df, wv[2], pre);
            pre = fmaf(fabsf(df), wv[3], pre);
            pre = fmaf(0.5f * (uL + uR), wv[4], pre);
            pre = fmaf(sg, wv[5], pre);
            s_zv[t * Hn + n] = pre;
        }
    }
    __syncthreads();
    ln_stats(s_zv, s_mu, s_rs, tid);
    if (tid < Hn) {
        float lg = ln_in_g[tid], lb = ln_in_b[tid];
        #pragma unroll
        for (int t = 0; t < 4; t++)
            s_h[t * Hn + tid] = gelu_f((s_zv[t * Hn + tid] - s_mu[t]) * s_rs[t] * lg + lb);
    }
    __syncthreads();

    // pipeline step prologue: tile j ready, prev compute done, issue j+2
    #define TILE_PROLOGUE(jglob)                                                  \
        CPA_WAIT(1);                                                              \
        __syncthreads();                                                          \
        if (gt < NTILES) {                                                        \
            copy_tile(smem + (gt % 3) * TILE_FLOATS, s_tiles[gt], tid);           \
            gt++;                                                                 \
        }

    // ---- 3 residual blocks ----
    for (int i = 0; i < 3; i++) {
        ln_stats(s_h, s_mu, s_rs, tid);
        if (tid < Hn) {
            float g = rb_ln_g[i * Hn + tid], bb = rb_ln_b[i * Hn + tid];
            #pragma unroll
            for (int t = 0; t < 4; t++)
                s_zv[t * Hn + tid] = (s_h[t * Hn + tid] - s_mu[t]) * s_rs[t] * g + bb;
        }
        // no sync here: first tile prologue below syncs before any cross-thread read

        // ===== GEMM1: zz[t][c] = gelu( sum_k z[t][k]*W1[k][c] + b1[c] ), c = tid
        {
            float acc0 = 0, acc1 = 0, acc2 = 0, acc3 = 0;
            #pragma unroll
            for (int t8 = 0; t8 < 8; t8++) {
                int jglob = i * 16 + t8;
                TILE_PROLOGUE(jglob);
                const float* cur = smem + (jglob % 3) * TILE_FLOATS;
                int k0 = t8 * 32;
                #pragma unroll
                for (int kk = 0; kk < 8; kk++) {
                    float4 z0 = *(const float4*)&s_zv[0 * Hn + k0 + kk * 4];
                    float4 z1 = *(const float4*)&s_zv[1 * Hn + k0 + kk * 4];
                    float4 z2 = *(const float4*)&s_zv[2 * Hn + k0 + kk * 4];
                    float4 z3 = *(const float4*)&s_zv[3 * Hn + k0 + kk * 4];
                    float w0 = cur[(kk * 4 + 0) * 512 + tid];
                    float w1v = cur[(kk * 4 + 1) * 512 + tid];
                    float w2v = cur[(kk * 4 + 2) * 512 + tid];
                    float w3v = cur[(kk * 4 + 3) * 512 + tid];
                    acc0 = fmaf(z0.x, w0, acc0); acc0 = fmaf(z0.y, w1v, acc0);
                    acc0 = fmaf(z0.z, w2v, acc0); acc0 = fmaf(z0.w, w3v, acc0);
                    acc1 = fmaf(z1.x, w0, acc1); acc1 = fmaf(z1.y, w1v, acc1);
                    acc1 = fmaf(z1.z, w2v, acc1); acc1 = fmaf(z1.w, w3v, acc1);
                    acc2 = fmaf(z2.x, w0, acc2); acc2 = fmaf(z2.y, w1v, acc2);
                    acc2 = fmaf(z2.z, w2v, acc2); acc2 = fmaf(z2.w, w3v, acc2);
                    acc3 = fmaf(z3.x, w0, acc3); acc3 = fmaf(z3.y, w1v, acc3);
                    acc3 = fmaf(z3.z, w2v, acc3); acc3 = fmaf(z3.w, w3v, acc3);
                }
            }
            __syncthreads();   // all reads of tile done before s_zz write visible order
            float bb = rb_b1[i * 2 * Hn + tid];
            s_zz[0 * 512 + tid] = gelu_f(acc0 + bb);
            s_zz[1 * 512 + tid] = gelu_f(acc1 + bb);
            s_zz[2 * 512 + tid] = gelu_f(acc2 + bb);
            s_zz[3 * 512 + tid] = gelu_f(acc3 + bb);
        }

        // ===== GEMM2: h[t][c] += sum_k zz[t][k]*W2[k][c] + b2[c]; split-K by 2
        {
            const int col = tid & 255, half = tid >> 8;
            float acc0 = 0, acc1 = 0, acc2 = 0, acc3 = 0;
            #pragma unroll
            for (int t8 = 0; t8 < 8; t8++) {
                int jglob = i * 16 + 8 + t8;
                TILE_PROLOGUE(jglob);
                const float* cur = smem + (jglob % 3) * TILE_FLOATS;
                int klocal = half * 32;
                int kglob  = t8 * 64 + klocal;
                #pragma unroll
                for (int kk = 0; kk < 8; kk++) {
                    float4 z0 = *(const float4*)&s_zz[0 * 512 + kglob + kk * 4];
                    float4 z1 = *(const float4*)&s_zz[1 * 512 + kglob + kk * 4];
                    float4 z2 = *(const float4*)&s_zz[2 * 512 + kglob + kk * 4];
                    float4 z3 = *(const float4*)&s_zz[3 * 512 + kglob + kk * 4];
                    float w0 = cur[(klocal + kk * 4 + 0) * 256 + col];
                    float w1v = cur[(klocal + kk * 4 + 1) * 256 + col];
                    float w2v = cur[(klocal + kk * 4 + 2) * 256 + col];
                    float w3v = cur[(klocal + kk * 4 + 3) * 256 + col];
                    acc0 = fmaf(z0.x, w0, acc0); acc0 = fmaf(z0.y, w1v, acc0);
                    acc0 = fmaf(z0.z, w2v, acc0); acc0 = fmaf(z0.w, w3v, acc0);
                    acc1 = fmaf(z1.x, w0, acc1); acc1 = fmaf(z1.y, w1v, acc1);
                    acc1 = fmaf(z1.z, w2v, acc1); acc1 = fmaf(z1.w, w3v, acc1);
                    acc2 = fmaf(z2.x, w0, acc2); acc2 = fmaf(z2.y, w1v, acc2);
                    acc2 = fmaf(z2.z, w2v, acc2); acc2 = fmaf(z2.w, w3v, acc2);
                    acc3 = fmaf(z3.x, w0, acc3); acc3 = fmaf(z3.y, w1v, acc3);
                    acc3 = fmaf(z3.z, w2v, acc3); acc3 = fmaf(z3.w, w3v, acc3);
                }
            }
            __syncthreads();
            if (half == 0) {
                s_zv[0 * Hn + col] = acc0;
                s_zv[1 * Hn + col] = acc1;
                s_zv[2 * Hn + col] = acc2;
                s_zv[3 * Hn + col] = acc3;
            }
            __syncthreads();
            if (half == 1) {
                float bq = rb_b2[i * Hn + col];
                s_h[0 * Hn + col] += s_zv[0 * Hn + col] + acc0 + bq;
                s_h[1 * Hn + col] += s_zv[1 * Hn + col] + acc1 + bq;
                s_h[2 * Hn + col] += s_zv[2 * Hn + col] + acc2 + bq;
                s_h[3 * Hn + col] += s_zv[3 * Hn + col] + acc3 + bq;
            }
            __syncthreads();
        }
    }

    // ---- output head ----
    ln_stats(s_h, s_mu, s_rs, tid);
    if (tid < Hn) {
        float og = out_ln_g[tid], ob = out_ln_b[tid];
        #pragma unroll
        for (int t = 0; t < 4; t++)
            s_zv[t * Hn + tid] = (s_h[t * Hn + tid] - s_mu[t]) * s_rs[t] * og + ob;
    }

    // a1 = gelu(z @ out_w1 + b1): tiles 48,49 already in the pipeline
    {
        const int col = tid & 127, kq = tid >> 7;
        float p0 = 0, p1 = 0, p2 = 0, p3 = 0;
        #pragma unroll
        for (int t8 = 0; t8 < 2; t8++) {
            int jglob = 48 + t8;
            if (t8 == 0) { CPA_WAIT(1); } else { CPA_WAIT(0); }
            __syncthreads();
            const float* cur = smem + (jglob % 3) * TILE_FLOATS;
            int kb = kq * 32;
            int zg = t8 * 128 + kb;
            #pragma unroll
            for (int kk = 0; kk < 8; kk++) {
                float4 z0 = *(const float4*)&s_zv[0 * Hn + zg + kk * 4];
                float4 z1 = *(const float4*)&s_zv[1 * Hn + zg + kk * 4];
                float4 z2 = *(const float4*)&s_zv[2 * Hn + zg + kk * 4];
                float4 z3 = *(const float4*)&s_zv[3 * Hn + zg + kk * 4];
                float w0 = cur[(kb + kk * 4 + 0) * 128 + col];
                float w1v = cur[(kb + kk * 4 + 1) * 128 + col];
                float w2v = cur[(kb + kk * 4 + 2) * 128 + col];
                float w3v = cur[(kb + kk * 4 + 3) * 128 + col];
                p0 = fmaf(z0.x, w0, p0); p0 = fmaf(z0.y, w1v, p0);
                p0 = fmaf(z0.z, w2v, p0); p0 = fmaf(z0.w, w3v, p0);
                p1 = fmaf(z1.x, w0, p1); p1 = fmaf(z1.y, w1v, p1);
                p1 = fmaf(z1.z, w2v, p1); p1 = fmaf(z1.w, w3v, p1);
                p2 = fmaf(z2.x, w0, p2); p2 = fmaf(z2.y, w1v, p2);
                p2 = fmaf(z2.z, w2v, p2); p2 = fmaf(z2.w, w3v, p2);
                p3 = fmaf(z3.x, w0, p3); p3 = fmaf(z3.y, w1v, p3);
                p3 = fmaf(z3.z, w2v, p3); p3 = fmaf(z3.w, w3v, p3);
            }
        }
        __syncthreads();
        s_zz[0 * 512 + kq * 128 + col] = p0;
        s_zz[1 * 512 + kq * 128 + col] = p1;
        s_zz[2 * 512 + kq * 128 + col] = p2;
        s_zz[3 * 512 + kq * 128 + col] = p3;
        __syncthreads();
        if (tid < 128) {
            float bo = out_b1[tid];
            #pragma unroll
            for (int t = 0; t < 4; t++) {
                float s = s_zz[t * 512 + tid] + s_zz[t * 512 + 128 + tid]
                        + s_zz[t * 512 + 256 + tid] + s_zz[t * 512 + 384 + tid] + bo;
                s_zv[t * Hn + tid] = gelu_f(s);
            }
        }
        __syncthreads();
    }

    // speed = a1 @ out_w2 + out_b2: warps 0..7 -> (token, col)
    {
        int w = tid >> 5, lane = tid & 31;
        if (w < 8) {
            int t = w >> 1, cc = w & 1;
            float s = 0.f;
            s = fmaf(s_zv[t * Hn + lane],      out_w2[lane * 2 + cc],        s);
            s = fmaf(s_zv[t * Hn + lane + 32], out_w2[(lane + 32) * 2 + cc], s);
            s = fmaf(s_zv[t * Hn + lane + 64], out_w2[(lane + 64) * 2 + cc], s);
            s = fmaf(s_zv[t * Hn + lane + 96], out_w2[(lane + 96) * 2 + cc], s);
            #pragma unroll
            for (int o = 16; o; o >>= 1) s += __shfl_xor_sync(0xffffffffu, s, o);
            if (lane == 0)
                out[b * 48 + cc * 8 + (kbase + t)] = s + out_b2[cc];
        }
    }
}

extern "C" void kernel_launch(void* const* d_in, const int* in_sizes, int n_in,
                              void* d_out, int out_size) {
    const float* x        = (const float*)d_in[0];
    const float* w_in     = (const float*)d_in[1];
    const float* b_in     = (const float*)d_in[2];
    const float* ln_in_g  = (const float*)d_in[3];
    const float* ln_in_b  = (const float*)d_in[4];
    const float* rb_ln_g  = (const float*)d_in[5];
    const float* rb_ln_b  = (const float*)d_in[6];
    const float* rb_w1    = (const float*)d_in[7];
    const float* rb_b1    = (const float*)d_in[8];
    const float* rb_w2    = (const float*)d_in[9];
    const float* rb_b2    = (const float*)d_in[10];
    const float* out_ln_g = (const float*)d_in[11];
    const float* out_ln_b = (const float*)d_in[12];
    const float* out_w1   = (const float*)d_in[13];
    const float* out_b1   = (const float*)d_in[14];
    const float* out_w2   = (const float*)d_in[15];
    const float* out_b2   = (const float*)d_in[16];
    float* out = (float*)d_out;

    // 3 ring tiles + h + z + zz
    const int smem_bytes = (3 * TILE_FLOATS + 4 * Hn + 4 * Hn + 4 * 512) * sizeof(float);
    cudaFuncSetAttribute(fused_all, cudaFuncAttributeMaxDynamicSharedMemorySize, smem_bytes);

    fused_all<<<148, NT, smem_bytes>>>(x, w_in, b_in, ln_in_g, ln_in_b,
                                       rb_ln_g, rb_ln_b, rb_w1, rb_b1, rb_w2, rb_b2,
                                       out_ln_g, out_ln_b, out_w1, out_b1, out_w2, out_b2,
                                       out);
}

// round 6
// speedup vs baseline: 2.2125x; 1.3074x over previous
#include <cuda_runtime.h>
#include <math.h>
#include <stdint.h>

#define Xn 262144
#define Bn 64
#define Hn 256
#define THRF 1e-6f
#define NT 512
#define TILE_FLOATS 16384   // 64KB weight tile
#define NTILES 50           // 3*16 residual tiles + 2 head tiles
#define CLU 4

// 2-party count handshake (zero-initialized; reset to 0 each run -> replay safe)
__device__ int g_part[Bn][2];
__device__ unsigned g_flag[Bn];

__device__ __forceinline__ float gelu_f(float v) {
    return 0.5f * v * (1.0f + erff(v * 0.70710678118654752f));
}

__device__ __forceinline__ uint32_t smem_u32(const void* p) {
    return (uint32_t)__cvta_generic_to_shared(p);
}

#define MBAR_INIT(addr, cnt) \
    asm volatile("mbarrier.init.shared.b64 [%0], %1;" :: "r"(addr), "r"(cnt) : "memory")
#define MBAR_EXPECT_TX(addr, bytes) \
    asm volatile("mbarrier.arrive.expect_tx.shared.b64 _, [%0], %1;" :: "r"(addr), "r"(bytes) : "memory")
#define MBAR_ARRIVE_CLUSTER(addr, rk) \
    asm volatile("{\n\t.reg .b32 ra%=;\n\tmapa.shared::cluster.u32 ra%=, %0, %1;\n\t" \
                 "mbarrier.arrive.shared::cluster.b64 _, [ra%=];\n\t}" \
                 :: "r"(addr), "r"(rk) : "memory")

__device__ __forceinline__ void mbar_wait(uint32_t addr, uint32_t parity) {
    asm volatile(
        "{\n\t.reg .pred P%=;\n\t"
        "WL%=:\n\t"
        "mbarrier.try_wait.parity.acquire.cta.shared::cta.b64 P%=, [%0], %1, 0x989680;\n\t"
        "@!P%= bra WL%=;\n\t}"
        :: "r"(addr), "r"(parity) : "memory");
}

// 16KB slice, multicast to all 4 cluster CTAs
__device__ __forceinline__ void bulk_mcast(uint32_t dst, const float* src, uint32_t mbar) {
    asm volatile(
        "cp.async.bulk.shared::cluster.global.mbarrier::complete_tx::bytes.multicast::cluster"
        " [%0], [%1], %2, [%3], %4;"
        :: "r"(dst), "l"(src), "r"(16384u), "r"(mbar), "h"((unsigned short)0xF)
        : "memory");
}

#define CLUSTER_SYNC_() do { \
    asm volatile("barrier.cluster.arrive.aligned;" ::: "memory"); \
    asm volatile("barrier.cluster.wait.aligned;" ::: "memory"); \
} while (0)

// LN stats over 4 tokens x 256; warp t (t<4) reduces token t
__device__ __forceinline__ void ln_stats(const float* buf, float* s_mu, float* s_rs, int tid) {
    int w = tid >> 5, lane = tid & 31;
    if (w < 4) {
        float s1 = 0.f, s2 = 0.f;
        #pragma unroll
        for (int j = 0; j < 8; j++) {
            float v = buf[w * Hn + lane + 32 * j];
            s1 += v;
            s2 = fmaf(v, v, s2);
        }
        #pragma unroll
        for (int o = 16; o; o >>= 1) {
            s1 += __shfl_xor_sync(0xffffffffu, s1, o);
            s2 += __shfl_xor_sync(0xffffffffu, s2, o);
        }
        if (lane == 0) {
            float mu = s1 * (1.f / 256.f);
            float var = fmaxf(s2 * (1.f / 256.f) - mu * mu, 0.f);
            s_mu[w] = mu;
            s_rs[w] = rsqrtf(var + 1e-5f);
        }
    }
    __syncthreads();
}

__global__ void __launch_bounds__(NT, 1) __cluster_dims__(CLU, 1, 1) fused_all(
    const float* __restrict__ x,
    const float* __restrict__ w_in,  const float* __restrict__ b_in,
    const float* __restrict__ ln_in_g, const float* __restrict__ ln_in_b,
    const float* __restrict__ rb_ln_g, const float* __restrict__ rb_ln_b,
    const float* __restrict__ rb_w1,  const float* __restrict__ rb_b1,
    const float* __restrict__ rb_w2,  const float* __restrict__ rb_b2,
    const float* __restrict__ out_ln_g, const float* __restrict__ out_ln_b,
    const float* __restrict__ out_w1, const float* __restrict__ out_b1,
    const float* __restrict__ out_w2, const float* __restrict__ out_b2,
    float* __restrict__ out)
{
    const int tid  = threadIdx.x;
    const uint32_t rank = (uint32_t)(blockIdx.x & 3);
    const int b     = blockIdx.x >> 1;
    const int half  = blockIdx.x & 1;
    const int kbase = half * 4;
    const float* d  = x + (size_t)b * 2 * Xn;
    const float* cr = d + Xn;

    extern __shared__ float smem[];
    float* s_h  = smem + 3 * TILE_FLOATS;   // 4*256
    float* s_zv = s_h + 4 * Hn;             // 4*256
    float* s_zz = s_zv + 4 * Hn;            // 4*512

    __shared__ uint64_t mb_full[3], mb_empty[3];
    __shared__ const float* s_tiles[NTILES];
    __shared__ float s_mu[4], s_rs[4];
    __shared__ float s_tk[2][4];
    __shared__ unsigned s_wm[16], s_vm[16];
    __shared__ int s_idx[8], s_non[8];
    __shared__ int s_nd, s_nn, s_done;
    __shared__ int cw[16];

    const uint32_t slot_base = smem_u32(smem);
    uint32_t mbf[3], mbe[3];
    #pragma unroll
    for (int s = 0; s < 3; s++) {
        mbf[s] = smem_u32(&mb_full[s]);
        mbe[s] = smem_u32(&mb_empty[s]);
    }

    if (tid == 0) {
        #pragma unroll
        for (int s = 0; s < 3; s++) {
            MBAR_INIT(mbf[s], 1u);
            MBAR_INIT(mbe[s], 4u);
        }
        s_nd = 0; s_nn = 0; s_done = 0;
    }
    if (tid < NTILES) {
        int j = tid;
        const float* p;
        if (j < 48) {
            int ph = j >> 4, w = j & 15;
            p = (w < 8) ? rb_w1 + (size_t)ph * 131072 + (size_t)w * TILE_FLOATS
                        : rb_w2 + (size_t)ph * 131072 + (size_t)(w - 8) * TILE_FLOATS;
        } else {
            p = out_w1 + (size_t)(j - 48) * TILE_FLOATS;
        }
        s_tiles[j] = p;
    }
    __syncthreads();
    CLUSTER_SYNC_();   // all mbarriers initialized cluster-wide

    int gt = 0;  // producer cursor (uniform across threads)

    #define TILE_ISSUE()                                                          \
        if (gt < NTILES) {                                                        \
            if (tid == 0) {                                                       \
                int ss = gt % 3;                                                  \
                mbar_wait(mbe[ss], (uint32_t)(((gt / 3) & 1) ^ 1));               \
                MBAR_EXPECT_TX(mbf[ss], 65536u);                                  \
                bulk_mcast(slot_base + (uint32_t)ss * 65536u + rank * 16384u,     \
                           s_tiles[gt] + rank * 4096, mbf[ss]);                   \
            }                                                                     \
            gt++;                                                                 \
        }

    // prime pipeline: tiles 0 and 1 in flight (land during scan/front-find)
    TILE_ISSUE();
    TILE_ISSUE();

    // ---- count scan: this block's half of batch row b (streaming) ----
    {
        const float4* d4 = (const float4*)d;
        const int start = half * (Xn / 2);
        const int iend  = half ? (Xn - 1) : (Xn / 2);
        int cnt = 0;
        #pragma unroll 4
        for (int it = 0; it < (Xn / 2) / (NT * 4); it++) {
            int i4 = (start >> 2) + tid + it * NT;
            float4 v = __ldcs(&d4[i4]);
            int j0 = i4 << 2;
            bool cross = (j0 + 3) < iend;
            float nxt = cross ? __ldcs(&d[j0 + 4]) : 0.f;
            cnt += (fabsf(v.x - v.y) > THRF);
            cnt += (fabsf(v.y - v.z) > THRF);
            cnt += (fabsf(v.z - v.w) > THRF);
            cnt += (cross && (fabsf(v.w - nxt) > THRF));
        }
        #pragma unroll
        for (int o = 16; o; o >>= 1) cnt += __shfl_xor_sync(0xffffffffu, cnt, o);
        if ((tid & 31) == 0) cw[tid >> 5] = cnt;
        __syncthreads();
        if (tid == 0) {
            int s = 0;
            #pragma unroll
            for (int w = 0; w < 16; w++) s += cw[w];
            g_part[b][half] = s;
            __threadfence();
            unsigned old = atomicAdd(&g_flag[b], 1u);
            if (old == 1u) {
                out[Bn * 48 + b] = (float)(s + g_part[b][half ^ 1]);
                g_flag[b] = 0u;   // reset for next graph replay
            }
        }
        __syncthreads();
    }

    // ---- find first 8 discontinuities (ordered) ----
    for (int base = 0; base < Xn - 1; base += NT) {
        int i = base + tid;
        bool valid = (i < Xn - 1);
        bool disc = valid && (fabsf(d[i] - d[i + 1]) > THRF);
        unsigned m  = __ballot_sync(0xffffffffu, disc);
        unsigned vm = __ballot_sync(0xffffffffu, valid);
        if ((tid & 31) == 0) { s_wm[tid >> 5] = m; s_vm[tid >> 5] = vm; }
        __syncthreads();
        if (tid == 0) {
            for (int w = 0; w < 16 && s_nd < 8; w++) {
                unsigned mm = s_wm[w], vv = s_vm[w];
                int ib = base + w * 32;
                while (vv) {
                    int lane = __ffs(vv) - 1;
                    vv &= vv - 1;
                    int idx = ib + lane;
                    if ((mm >> lane) & 1u) {
                        if (s_nd < 8) {
                            s_idx[s_nd++] = idx;
                            if (s_nd >= 8) break;
                        }
                    } else {
                        if (s_nn < 8) s_non[s_nn++] = idx;
                    }
                }
            }
            if (s_nd >= 8) s_done = 1;
        }
        __syncthreads();
        if (s_done) break;
    }
    if (tid < 4) {
        int k = kbase + tid;
        int nd = s_nd;
        int i; float vf;
        if (k < nd) { i = s_idx[k]; vf = 1.0f; }
        else        { i = s_non[k - nd]; vf = 0.0f; }
        float uL = d[i], uR = d[i + 1];
        float fc = 0.5f * (cr[i] + cr[i + 1]);
        s_tk[0][tid] = uL;
        s_tk[1][tid] = uR;
        int base = b * 48;
        out[base + 16 + k] = uL;
        out[base + 24 + k] = uR;
        out[base + 32 + k] = fc;
        out[base + 40 + k] = vf;
    }
    __syncthreads();

    // ---- input layer ----
    if (tid < Hn) {
        int n = tid;
        float wv[6];
        #pragma unroll
        for (int f = 0; f < 6; f++) wv[f] = w_in[f * Hn + n];
        float bi = b_in[n];
        #pragma unroll
        for (int t = 0; t < 4; t++) {
            float uL = s_tk[0][t], uR = s_tk[1][t];
            float df = uL - uR;
            float sg = (df > 0.f) ? 1.f : ((df < 0.f) ? -1.f : 0.f);
            float pre = bi;
            pre = fmaf(uL, wv[0], pre);
            pre = fmaf(uR, wv[1], pre);
            pre = fmaf(df, wv[2], pre);
            pre = fmaf(fabsf(df), wv[3], pre);
            pre = fmaf(0.5f * (uL + uR), wv[4], pre);
            pre = fmaf(sg, wv[5], pre);
            s_zv[t * Hn + n] = pre;
        }
    }
    __syncthreads();
    ln_stats(s_zv, s_mu, s_rs, tid);
    if (tid < Hn) {
        float lg = ln_in_g[tid], lb = ln_in_b[tid];
        #pragma unroll
        for (int t = 0; t < 4; t++)
            s_h[t * Hn + tid] = gelu_f((s_zv[t * Hn + tid] - s_mu[t]) * s_rs[t] * lg + lb);
    }
    __syncthreads();

    // consume tile j from its ring slot; release slot afterwards
    #define TILE_RELEASE(jglob)                                                   \
        __syncthreads();                                                          \
        if (tid == 0) {                                                           \
            int ss = (jglob) % 3;                                                 \
            MBAR_ARRIVE_CLUSTER(mbe[ss], 0u);                                     \
            MBAR_ARRIVE_CLUSTER(mbe[ss], 1u);                                     \
            MBAR_ARRIVE_CLUSTER(mbe[ss], 2u);                                     \
            MBAR_ARRIVE_CLUSTER(mbe[ss], 3u);                                     \
        }

    // ---- 3 residual blocks ----
    for (int i = 0; i < 3; i++) {
        ln_stats(s_h, s_mu, s_rs, tid);
        if (tid < Hn) {
            float g = rb_ln_g[i * Hn + tid], bb = rb_ln_b[i * Hn + tid];
            #pragma unroll
            for (int t = 0; t < 4; t++)
                s_zv[t * Hn + tid] = (s_h[t * Hn + tid] - s_mu[t]) * s_rs[t] * g + bb;
        }
        __syncthreads();

        // ===== GEMM1: zz[t][c] = gelu(sum_k z[t][k]*W1[k][c] + b1[c]), c = tid
        {
            float acc0 = 0, acc1 = 0, acc2 = 0, acc3 = 0;
            #pragma unroll
            for (int t8 = 0; t8 < 8; t8++) {
                int jglob = i * 16 + t8;
                TILE_ISSUE();
                mbar_wait(mbf[jglob % 3], (uint32_t)((jglob / 3) & 1));
                const float* cur = smem + (jglob % 3) * TILE_FLOATS;
                int k0 = t8 * 32;
                #pragma unroll
                for (int kk = 0; kk < 8; kk++) {
                    float4 z0 = *(const float4*)&s_zv[0 * Hn + k0 + kk * 4];
                    float4 z1 = *(const float4*)&s_zv[1 * Hn + k0 + kk * 4];
                    float4 z2 = *(const float4*)&s_zv[2 * Hn + k0 + kk * 4];
                    float4 z3 = *(const float4*)&s_zv[3 * Hn + k0 + kk * 4];
                    float w0 = cur[(kk * 4 + 0) * 512 + tid];
                    float w1v = cur[(kk * 4 + 1) * 512 + tid];
                    float w2v = cur[(kk * 4 + 2) * 512 + tid];
                    float w3v = cur[(kk * 4 + 3) * 512 + tid];
                    acc0 = fmaf(z0.x, w0, acc0); acc0 = fmaf(z0.y, w1v, acc0);
                    acc0 = fmaf(z0.z, w2v, acc0); acc0 = fmaf(z0.w, w3v, acc0);
                    acc1 = fmaf(z1.x, w0, acc1); acc1 = fmaf(z1.y, w1v, acc1);
                    acc1 = fmaf(z1.z, w2v, acc1); acc1 = fmaf(z1.w, w3v, acc1);
                    acc2 = fmaf(z2.x, w0, acc2); acc2 = fmaf(z2.y, w1v, acc2);
                    acc2 = fmaf(z2.z, w2v, acc2); acc2 = fmaf(z2.w, w3v, acc2);
                    acc3 = fmaf(z3.x, w0, acc3); acc3 = fmaf(z3.y, w1v, acc3);
                    acc3 = fmaf(z3.z, w2v, acc3); acc3 = fmaf(z3.w, w3v, acc3);
                }
                TILE_RELEASE(jglob);
            }
            float bb = rb_b1[i * 2 * Hn + tid];
            s_zz[0 * 512 + tid] = gelu_f(acc0 + bb);
            s_zz[1 * 512 + tid] = gelu_f(acc1 + bb);
            s_zz[2 * 512 + tid] = gelu_f(acc2 + bb);
            s_zz[3 * 512 + tid] = gelu_f(acc3 + bb);
            __syncthreads();
        }

        // ===== GEMM2: h[t][c] += sum_k zz[t][k]*W2[k][c] + b2[c]; split-K by 2
        {
            const int col = tid & 255, hf = tid >> 8;
            float acc0 = 0, acc1 = 0, acc2 = 0, acc3 = 0;
            #pragma unroll
            for (int t8 = 0; t8 < 8; t8++) {
                int jglob = i * 16 + 8 + t8;
                TILE_ISSUE();
                mbar_wait(mbf[jglob % 3], (uint32_t)((jglob / 3) & 1));
                const float* cur = smem + (jglob % 3) * TILE_FLOATS;
                int klocal = hf * 32;
                int kglob  = t8 * 64 + klocal;
                #pragma unroll
                for (int kk = 0; kk < 8; kk++) {
                    float4 z0 = *(const float4*)&s_zz[0 * 512 + kglob + kk * 4];
                    float4 z1 = *(const float4*)&s_zz[1 * 512 + kglob + kk * 4];
                    float4 z2 = *(const float4*)&s_zz[2 * 512 + kglob + kk * 4];
                    float4 z3 = *(const float4*)&s_zz[3 * 512 + kglob + kk * 4];
                    float w0 = cur[(klocal + kk * 4 + 0) * 256 + col];
                    float w1v = cur[(klocal + kk * 4 + 1) * 256 + col];
                    float w2v = cur[(klocal + kk * 4 + 2) * 256 + col];
                    float w3v = cur[(klocal + kk * 4 + 3) * 256 + col];
                    acc0 = fmaf(z0.x, w0, acc0); acc0 = fmaf(z0.y, w1v, acc0);
                    acc0 = fmaf(z0.z, w2v, acc0); acc0 = fmaf(z0.w, w3v, acc0);
                    acc1 = fmaf(z1.x, w0, acc1); acc1 = fmaf(z1.y, w1v, acc1);
                    acc1 = fmaf(z1.z, w2v, acc1); acc1 = fmaf(z1.w, w3v, acc1);
                    acc2 = fmaf(z2.x, w0, acc2); acc2 = fmaf(z2.y, w1v, acc2);
                    acc2 = fmaf(z2.z, w2v, acc2); acc2 = fmaf(z2.w, w3v, acc2);
                    acc3 = fmaf(z3.x, w0, acc3); acc3 = fmaf(z3.y, w1v, acc3);
                    acc3 = fmaf(z3.z, w2v, acc3); acc3 = fmaf(z3.w, w3v, acc3);
                }
                TILE_RELEASE(jglob);
            }
            __syncthreads();
            if (hf == 0) {
                s_zv[0 * Hn + col] = acc0;
                s_zv[1 * Hn + col] = acc1;
                s_zv[2 * Hn + col] = acc2;
                s_zv[3 * Hn + col] = acc3;
            }
            __syncthreads();
            if (hf == 1) {
                float bq = rb_b2[i * Hn + col];
                s_h[0 * Hn + col] += s_zv[0 * Hn + col] + acc0 + bq;
                s_h[1 * Hn + col] += s_zv[1 * Hn + col] + acc1 + bq;
                s_h[2 * Hn + col] += s_zv[2 * Hn + col] + acc2 + bq;
                s_h[3 * Hn + col] += s_zv[3 * Hn + col] + acc3 + bq;
            }
            __syncthreads();
        }
    }

    // ---- output head ----
    ln_stats(s_h, s_mu, s_rs, tid);
    if (tid < Hn) {
        float og = out_ln_g[tid], ob = out_ln_b[tid];
        #pragma unroll
        for (int t = 0; t < 4; t++)
            s_zv[t * Hn + tid] = (s_h[t * Hn + tid] - s_mu[t]) * s_rs[t] * og + ob;
    }
    __syncthreads();

    // a1 = gelu(z @ out_w1 + b1): tiles 48,49 already streaming
    {
        const int col = tid & 127, kq = tid >> 7;
        float p0 = 0, p1 = 0, p2 = 0, p3 = 0;
        #pragma unroll
        for (int t8 = 0; t8 < 2; t8++) {
            int jglob = 48 + t8;
            TILE_ISSUE();   // no-op (gt == 50), keeps gt uniform
            mbar_wait(mbf[jglob % 3], (uint32_t)((jglob / 3) & 1));
            const float* cur = smem + (jglob % 3) * TILE_FLOATS;
            int kb = kq * 32;
            int zg = t8 * 128 + kb;
            #pragma unroll
            for (int kk = 0; kk < 8; kk++) {
                float4 z0 = *(const float4*)&s_zv[0 * Hn + zg + kk * 4];
                float4 z1 = *(const float4*)&s_zv[1 * Hn + zg + kk * 4];
                float4 z2 = *(const float4*)&s_zv[2 * Hn + zg + kk * 4];
                float4 z3 = *(const float4*)&s_zv[3 * Hn + zg + kk * 4];
                float w0 = cur[(kb + kk * 4 + 0) * 128 + col];
                float w1v = cur[(kb + kk * 4 + 1) * 128 + col];
                float w2v = cur[(kb + kk * 4 + 2) * 128 + col];
                float w3v = cur[(kb + kk * 4 + 3) * 128 + col];
                p0 = fmaf(z0.x, w0, p0); p0 = fmaf(z0.y, w1v, p0);
                p0 = fmaf(z0.z, w2v, p0); p0 = fmaf(z0.w, w3v, p0);
                p1 = fmaf(z1.x, w0, p1); p1 = fmaf(z1.y, w1v, p1);
                p1 = fmaf(z1.z, w2v, p1); p1 = fmaf(z1.w, w3v, p1);
                p2 = fmaf(z2.x, w0, p2); p2 = fmaf(z2.y, w1v, p2);
                p2 = fmaf(z2.z, w2v, p2); p2 = fmaf(z2.w, w3v, p2);
                p3 = fmaf(z3.x, w0, p3); p3 = fmaf(z3.y, w1v, p3);
                p3 = fmaf(z3.z, w2v, p3); p3 = fmaf(z3.w, w3v, p3);
            }
            TILE_RELEASE(jglob);
        }
        s_zz[0 * 512 + kq * 128 + col] = p0;
        s_zz[1 * 512 + kq * 128 + col] = p1;
        s_zz[2 * 512 + kq * 128 + col] = p2;
        s_zz[3 * 512 + kq * 128 + col] = p3;
        __syncthreads();
        if (tid < 128) {
            float bo = out_b1[tid];
            #pragma unroll
            for (int t = 0; t < 4; t++) {
                float s = s_zz[t * 512 + tid] + s_zz[t * 512 + 128 + tid]
                        + s_zz[t * 512 + 256 + tid] + s_zz[t * 512 + 384 + tid] + bo;
                s_zv[t * Hn + tid] = gelu_f(s);
            }
        }
        __syncthreads();
    }

    // speed = a1 @ out_w2 + out_b2: warps 0..7 -> (token, col)
    {
        int w = tid >> 5, lane = tid & 31;
        if (w < 8) {
            int t = w >> 1, cc = w & 1;
            float s = 0.f;
            s = fmaf(s_zv[t * Hn + lane],      out_w2[lane * 2 + cc],        s);
            s = fmaf(s_zv[t * Hn + lane + 32], out_w2[(lane + 32) * 2 + cc], s);
            s = fmaf(s_zv[t * Hn + lane + 64], out_w2[(lane + 64) * 2 + cc], s);
            s = fmaf(s_zv[t * Hn + lane + 96], out_w2[(lane + 96) * 2 + cc], s);
            #pragma unroll
            for (int o = 16; o; o >>= 1) s += __shfl_xor_sync(0xffffffffu, s, o);
            if (lane == 0)
                out[b * 48 + cc * 8 + (kbase + t)] = s + out_b2[cc];
        }
    }

    // no CTA may exit while cluster peers can still arrive on its mbarriers
    CLUSTER_SYNC_();
}

extern "C" void kernel_launch(void* const* d_in, const int* in_sizes, int n_in,
                              void* d_out, int out_size) {
    const float* x        = (const float*)d_in[0];
    const float* w_in     = (const float*)d_in[1];
    const float* b_in     = (const float*)d_in[2];
    const float* ln_in_g  = (const float*)d_in[3];
    const float* ln_in_b  = (const float*)d_in[4];
    const float* rb_ln_g  = (const float*)d_in[5];
    const float* rb_ln_b  = (const float*)d_in[6];
    const float* rb_w1    = (const float*)d_in[7];
    const float* rb_b1    = (const float*)d_in[8];
    const float* rb_w2    = (const float*)d_in[9];
    const float* rb_b2    = (const float*)d_in[10];
    const float* out_ln_g = (const float*)d_in[11];
    const float* out_ln_b = (const float*)d_in[12];
    const float* out_w1   = (const float*)d_in[13];
    const float* out_b1   = (const float*)d_in[14];
    const float* out_w2   = (const float*)d_in[15];
    const float* out_b2   = (const float*)d_in[16];
    float* out = (float*)d_out;

    // 3 ring tiles (192KB) + h + z + zz
    const int smem_bytes = (3 * TILE_FLOATS + 4 * Hn + 4 * Hn + 4 * 512) * sizeof(float);
    cudaFuncSetAttribute(fused_all, cudaFuncAttributeMaxDynamicSharedMemorySize, smem_bytes);

    fused_all<<<128, NT, smem_bytes>>>(x, w_in, b_in, ln_in_g, ln_in_b,
                                       rb_ln_g, rb_ln_b, rb_w1, rb_b1, rb_w2, rb_b2,
                                       out_ln_g, out_ln_b, out_w1, out_b1, out_w2, out_b2,
                                       out);
}